// round 3
// baseline (speedup 1.0000x reference)
#include <cuda_runtime.h>
#include <math.h>

#define Gg   256
#define Nn   512
#define Ee   4096
#define FIN  64
#define FOUT 64
#define Cc   16
#define NK   (Nn * FOUT)          // 32768 flat features per graph
#define QCSR (Ee + 128)           // worst-case CSR entries per node-quarter

// ---------------- scratch ----------------
__device__ float g_xw[(size_t)Gg * Nn * FOUT];     // x @ W^T
__device__ float g_h [(size_t)Gg * Nn * FOUT];     // relu(aggregate + bias)
__device__ float g_logits[(size_t)Gg * Cc];        // split-K partial logits

// ---------------------------------------------------------------------------
// K1: per-graph GEMM  xw[g] = x[g] (512x64) @ W^T (64x64)   (FFMA-bound)
// ---------------------------------------------------------------------------
__global__ __launch_bounds__(256) void k1_xw(const float* __restrict__ x,
                                             const float* __restrict__ w)
{
    __shared__ float Xt[64 * 68];   // Xt[k][n]
    __shared__ float Wt[64 * 68];   // Wt[k][o]

    const int g     = blockIdx.y;
    const int nbase = blockIdx.x * 64;
    const int t     = threadIdx.x;

    const float* xg = x + ((size_t)g * Nn + nbase) * FIN;

    for (int i = t; i < 4096; i += 256) {
        int r = i >> 6, k = i & 63;
        Xt[k * 68 + r] = xg[r * FIN + k];
        Wt[k * 68 + r] = w[r * FIN + k];
    }
    __syncthreads();

    const int o0 = (t & 15) * 4;
    const int n0 = (t >> 4) * 4;

    float acc[4][4];
    #pragma unroll
    for (int i = 0; i < 4; i++)
        #pragma unroll
        for (int j = 0; j < 4; j++) acc[i][j] = 0.f;

    #pragma unroll 8
    for (int k = 0; k < 64; k++) {
        float4 xv = *(const float4*)&Xt[k * 68 + n0];
        float4 wv = *(const float4*)&Wt[k * 68 + o0];
        float xs[4] = {xv.x, xv.y, xv.z, xv.w};
        float ws[4] = {wv.x, wv.y, wv.z, wv.w};
        #pragma unroll
        for (int i = 0; i < 4; i++)
            #pragma unroll
            for (int j = 0; j < 4; j++)
                acc[i][j] = fmaf(xs[i], ws[j], acc[i][j]);
    }

    float* outp = g_xw + ((size_t)g * Nn + nbase) * FOUT;
    #pragma unroll
    for (int i = 0; i < 4; i++)
        *(float4*)&outp[(size_t)(n0 + i) * FOUT + o0] =
            make_float4(acc[i][0], acc[i][1], acc[i][2], acc[i][3]);
}

// ---------------------------------------------------------------------------
// K2: grid (G, 4). Each block: full degree count (smem), quarter CSR in smem,
//     aggregate 128 nodes (warp-per-node) + bias + ReLU -> h. No global CSR.
// ---------------------------------------------------------------------------
__global__ __launch_bounds__(512) void k2_agg(const int*   __restrict__ ei,
                                              const float* __restrict__ conv_bias)
{
    __shared__ int   cnt[Nn];
    __shared__ float dinv[Nn];
    __shared__ int   sc[128];
    __shared__ int   offx[129];
    __shared__ int   wcur[128];
    __shared__ int   srow[QCSR];
    __shared__ float snorm[QCSR];
    __shared__ float bias_s[FOUT];

    const int g   = blockIdx.x;
    const int q   = blockIdx.y;           // node quarter 0..3
    const int tid = threadIdx.x;

    const int* rowp = ei + (size_t)g * 2 * Ee;
    const int* colp = rowp + Ee;

    // full degree count (needed for dinv of ALL nodes)
    cnt[tid] = 1;                          // self-loop
    __syncthreads();
    for (int e = tid; e < Ee; e += 512)
        atomicAdd(&cnt[colp[e]], 1);
    __syncthreads();
    dinv[tid] = rsqrtf((float)cnt[tid]);
    __syncthreads();

    // scan over this quarter's 128 degree bins
    if (tid < 128) sc[tid] = cnt[q * 128 + tid];
    __syncthreads();
    for (int s = 1; s < 128; s <<= 1) {
        int v = (tid < 128 && tid >= s) ? sc[tid - s] : 0;
        __syncthreads();
        if (tid < 128) sc[tid] += v;
        __syncthreads();
    }
    if (tid < 128) {
        const int n    = q * 128 + tid;
        const int incl = sc[tid];
        const int excl = incl - cnt[n];
        offx[tid + 1] = incl;
        srow[excl]  = n;                   // self-loop first
        snorm[excl] = dinv[n] * dinv[n];
        wcur[tid]   = excl + 1;
    }
    if (tid == 0) offx[0] = 0;
    if (tid < FOUT) bias_s[tid] = conv_bias[tid];
    if (q == 0 && tid < Cc) g_logits[g * Cc + tid] = 0.f;
    __syncthreads();

    // scatter only edges targeting this quarter
    for (int e = tid; e < Ee; e += 512) {
        int c = colp[e];
        if ((c >> 7) == q) {
            int r   = rowp[e];
            int pos = atomicAdd(&wcur[c & 127], 1);
            srow[pos]  = r;
            snorm[pos] = dinv[r] * dinv[c];
        }
    }
    __syncthreads();

    // aggregate: warp-per-node, 8 nodes/warp, dual accumulators (MLP=2)
    const float2* xw2 = (const float2*)(g_xw + (size_t)g * NK);
    float2*       h2  = (float2*)      (g_h  + (size_t)g * NK);
    const int wid  = tid >> 5;
    const int lane = tid & 31;
    const float bx0 = bias_s[lane * 2];
    const float bx1 = bias_s[lane * 2 + 1];

    for (int ln = wid; ln < 128; ln += 16) {
        const int n  = q * 128 + ln;
        const int b  = offx[ln];
        const int e2 = offx[ln + 1];

        float ax = 0.f, ay = 0.f, cx = 0.f, cy = 0.f;
        int j = b;
        for (; j + 2 <= e2; j += 2) {
            int   r0  = srow[j],  r1  = srow[j + 1];
            float nm0 = snorm[j], nm1 = snorm[j + 1];
            float2 v0 = __ldg(&xw2[r0 * 32 + lane]);
            float2 v1 = __ldg(&xw2[r1 * 32 + lane]);
            ax = fmaf(v0.x, nm0, ax);  ay = fmaf(v0.y, nm0, ay);
            cx = fmaf(v1.x, nm1, cx);  cy = fmaf(v1.y, nm1, cy);
        }
        if (j < e2) {
            int   r  = srow[j];
            float nm = snorm[j];
            float2 v = __ldg(&xw2[r * 32 + lane]);
            ax = fmaf(v.x, nm, ax);  ay = fmaf(v.y, nm, ay);
        }
        ax += cx;  ay += cy;
        ax = fmaxf(ax + bx0, 0.f);
        ay = fmaxf(ay + bx1, 0.f);
        h2[n * 32 + lane] = make_float2(ax, ay);
    }
}

// ---------------------------------------------------------------------------
// K3: classifier  logits += h[G,32768] @ lw[C,32768]^T
//     No smem tiles. lane = (class, ksub); h loads are half-warp-uniform;
//     16 graphs per thread -> 64 independent FMAs per lw load. FFMA-bound.
//     grid (32 ksplit, 16 gtiles), block 256 (8 warps = 16 k-streams).
// ---------------------------------------------------------------------------
#define K3_GT 16
__global__ __launch_bounds__(256) void k3_cls(const float* __restrict__ lw)
{
    __shared__ float red[8 * 256];

    const int tid  = threadIdx.x;
    const int wid  = tid >> 5;
    const int lane = tid & 31;
    const int c    = lane & 15;
    const int ksub = lane >> 4;

    const int g0     = blockIdx.y * K3_GT;
    const int stream = wid * 2 + ksub;                       // 0..15
    const int k4base = (blockIdx.x * 1024 + stream * 64) >> 2; // float4 index

    float acc[K3_GT];
    #pragma unroll
    for (int g = 0; g < K3_GT; g++) acc[g] = 0.f;

    const float4* lw4 = (const float4*)(lw + (size_t)c * NK);

    #pragma unroll 4
    for (int j = 0; j < 16; j++) {
        const int k4 = k4base + j;
        float4 w = __ldg(&lw4[k4]);
        #pragma unroll
        for (int g = 0; g < K3_GT; g++) {
            float4 hv = __ldg((const float4*)(g_h + (size_t)(g0 + g) * NK) + k4);
            acc[g] = fmaf(hv.x, w.x,
                     fmaf(hv.y, w.y,
                     fmaf(hv.z, w.z,
                     fmaf(hv.w, w.w, acc[g]))));
        }
    }

    // fold the two k-subgroups
    #pragma unroll
    for (int g = 0; g < K3_GT; g++)
        acc[g] += __shfl_xor_sync(0xffffffffu, acc[g], 16);

    if (lane < 16) {
        #pragma unroll
        for (int g = 0; g < K3_GT; g++)
            red[wid * 256 + c * 16 + g] = acc[g];
    }
    __syncthreads();

    // tid = c*16 + g : reduce 8 warps, one atomic per (g,c)
    float s = 0.f;
    #pragma unroll
    for (int w = 0; w < 8; w++) s += red[w * 256 + tid];
    const int gg = tid & 15;
    const int cc = tid >> 4;
    atomicAdd(&g_logits[(size_t)(g0 + gg) * Cc + cc], s);
}

// ---------------------------------------------------------------------------
// K4: bias + log_softmax over [G, 16]
// ---------------------------------------------------------------------------
__global__ __launch_bounds__(256) void k4_lsm(const float* __restrict__ lb,
                                              float* __restrict__ out)
{
    const int tid = threadIdx.x;
    const int g   = blockIdx.x * 16 + (tid >> 4);
    const int c   = tid & 15;

    float s = g_logits[g * Cc + c] + lb[c];
    float m = s;
    #pragma unroll
    for (int o = 8; o > 0; o >>= 1)
        m = fmaxf(m, __shfl_xor_sync(0xffffffffu, m, o, 16));
    float se = expf(s - m);
    #pragma unroll
    for (int o = 8; o > 0; o >>= 1)
        se += __shfl_xor_sync(0xffffffffu, se, o, 16);
    out[g * Cc + c] = (s - m) - logf(se);
}

// ---------------------------------------------------------------------------
extern "C" void kernel_launch(void* const* d_in, const int* in_sizes, int n_in,
                              void* d_out, int out_size)
{
    const float* x  = (const float*)d_in[0];   // [G, N, F_IN]
    const int*   ei = (const int*)  d_in[1];   // [G, 2, E]
    const float* cw = (const float*)d_in[2];   // [F_OUT, F_IN]
    const float* cb = (const float*)d_in[3];   // [F_OUT]
    const float* lw = (const float*)d_in[4];   // [C, N*F_OUT]
    const float* lb = (const float*)d_in[5];   // [C]
    float* out = (float*)d_out;                // [G, C]

    k1_xw <<<dim3(Nn / 64, Gg), 256>>>(x, cw);
    k2_agg<<<dim3(Gg, 4), 512>>>(ei, cb);
    k3_cls<<<dim3(32, Gg / K3_GT), 256>>>(lw);
    k4_lsm<<<Gg / 16, 256>>>(lb, out);
}

// round 4
// speedup vs baseline: 1.4486x; 1.4486x over previous
#include <cuda_runtime.h>
#include <math.h>

#define Gg   256
#define Nn   512
#define Ee   4096
#define FIN  64
#define FOUT 64
#define Cc   16
#define NK   (Nn * FOUT)          // 32768 flat features per graph
#define HN   256                  // nodes per k2 block (half graph)
#define HCSR (Ee + HN)            // worst-case CSR entries per half

// ---------------- scratch ----------------
__device__ float g_xw[(size_t)Gg * Nn * FOUT];     // x @ W^T
__device__ float g_h [(size_t)Gg * Nn * FOUT];     // relu(aggregate + bias)
__device__ float g_logits[(size_t)Gg * Cc];        // split-K partial logits

// ---------------------------------------------------------------------------
// K1: per-graph GEMM  xw[g] = x[g] (512x64) @ W^T (64x64)   (FFMA-bound)
// ---------------------------------------------------------------------------
__global__ __launch_bounds__(256) void k1_xw(const float* __restrict__ x,
                                             const float* __restrict__ w)
{
    __shared__ float Xt[64 * 68];   // Xt[k][n]
    __shared__ float Wt[64 * 68];   // Wt[k][o]

    const int g     = blockIdx.y;
    const int nbase = blockIdx.x * 64;
    const int t     = threadIdx.x;

    const float* xg = x + ((size_t)g * Nn + nbase) * FIN;

    for (int i = t; i < 4096; i += 256) {
        int r = i >> 6, k = i & 63;
        Xt[k * 68 + r] = xg[r * FIN + k];
        Wt[k * 68 + r] = w[r * FIN + k];
    }
    __syncthreads();

    const int o0 = (t & 15) * 4;
    const int n0 = (t >> 4) * 4;

    float acc[4][4];
    #pragma unroll
    for (int i = 0; i < 4; i++)
        #pragma unroll
        for (int j = 0; j < 4; j++) acc[i][j] = 0.f;

    #pragma unroll 8
    for (int k = 0; k < 64; k++) {
        float4 xv = *(const float4*)&Xt[k * 68 + n0];
        float4 wv = *(const float4*)&Wt[k * 68 + o0];
        float xs[4] = {xv.x, xv.y, xv.z, xv.w};
        float ws[4] = {wv.x, wv.y, wv.z, wv.w};
        #pragma unroll
        for (int i = 0; i < 4; i++)
            #pragma unroll
            for (int j = 0; j < 4; j++)
                acc[i][j] = fmaf(xs[i], ws[j], acc[i][j]);
    }

    float* outp = g_xw + ((size_t)g * Nn + nbase) * FOUT;
    #pragma unroll
    for (int i = 0; i < 4; i++)
        *(float4*)&outp[(size_t)(n0 + i) * FOUT + o0] =
            make_float4(acc[i][0], acc[i][1], acc[i][2], acc[i][3]);
}

// ---------------------------------------------------------------------------
// K2: grid (G, 2). Degree count (full graph) + half-graph CSR in smem,
//     warp-per-node aggregation + bias + ReLU -> h.  (R1's proven structure,
//     classifier removed, 2x block parallelism, unroll-4 accumulators)
// ---------------------------------------------------------------------------
__global__ __launch_bounds__(512) void k2_agg(const int*   __restrict__ ei,
                                              const float* __restrict__ conv_bias)
{
    __shared__ int   cnt[Nn];
    __shared__ float dinv[Nn];
    __shared__ int   sc[HN];
    __shared__ int   offx[HN + 1];
    __shared__ int   wcur[HN];
    __shared__ int   srow[HCSR];
    __shared__ float snorm[HCSR];
    __shared__ float bias_s[FOUT];

    const int g   = blockIdx.x;
    const int q   = blockIdx.y;           // half 0..1
    const int tid = threadIdx.x;

    const int* rowp = ei + (size_t)g * 2 * Ee;   // sources
    const int* colp = rowp + Ee;                 // targets

    // --- full degree count (dinv needed for ALL source nodes) ---
    cnt[tid] = 1;                          // self-loop
    __syncthreads();
    for (int e = tid; e < Ee; e += 512)
        atomicAdd(&cnt[colp[e]], 1);
    __syncthreads();
    dinv[tid] = rsqrtf((float)cnt[tid]);
    __syncthreads();

    // --- scan over this half's 256 degree bins ---
    if (tid < HN) sc[tid] = cnt[q * HN + tid];
    __syncthreads();
    for (int s = 1; s < HN; s <<= 1) {
        int v = (tid < HN && tid >= s) ? sc[tid - s] : 0;
        __syncthreads();
        if (tid < HN) sc[tid] += v;
        __syncthreads();
    }
    if (tid < HN) {
        const int n    = q * HN + tid;
        const int incl = sc[tid];
        const int excl = incl - cnt[n];
        offx[tid + 1] = incl;
        srow[excl]  = n;                   // self-loop first entry
        snorm[excl] = dinv[n] * dinv[n];
        wcur[tid]   = excl + 1;
    }
    if (tid == 0) offx[0] = 0;
    if (tid < FOUT) bias_s[tid] = conv_bias[tid];
    if (q == 0 && tid < Cc) g_logits[g * Cc + tid] = 0.f;
    __syncthreads();

    // --- scatter edges targeting this half ---
    for (int e = tid; e < Ee; e += 512) {
        int c = colp[e];
        if ((c >> 8) == q) {
            int r   = rowp[e];
            int pos = atomicAdd(&wcur[c & (HN - 1)], 1);
            srow[pos]  = r;
            snorm[pos] = dinv[r] * dinv[c];
        }
    }
    __syncthreads();

    // --- aggregate: warp-per-node, 16 nodes/warp, quad accumulators (MLP=4) ---
    const float2* xw2 = (const float2*)(g_xw + (size_t)g * NK);
    float2*       h2  = (float2*)      (g_h  + (size_t)g * NK);
    const int wid  = tid >> 5;
    const int lane = tid & 31;
    const float bx0 = bias_s[lane * 2];
    const float bx1 = bias_s[lane * 2 + 1];

    for (int ln = wid; ln < HN; ln += 16) {
        const int n  = q * HN + ln;
        const int b  = offx[ln];
        const int e2 = offx[ln + 1];

        float a0x = 0.f, a0y = 0.f, a1x = 0.f, a1y = 0.f;
        float a2x = 0.f, a2y = 0.f, a3x = 0.f, a3y = 0.f;
        int j = b;
        for (; j + 4 <= e2; j += 4) {
            int   r0 = srow[j],   r1 = srow[j+1], r2 = srow[j+2], r3 = srow[j+3];
            float m0 = snorm[j],  m1 = snorm[j+1], m2 = snorm[j+2], m3 = snorm[j+3];
            float2 v0 = __ldg(&xw2[r0 * 32 + lane]);
            float2 v1 = __ldg(&xw2[r1 * 32 + lane]);
            float2 v2 = __ldg(&xw2[r2 * 32 + lane]);
            float2 v3 = __ldg(&xw2[r3 * 32 + lane]);
            a0x = fmaf(v0.x, m0, a0x);  a0y = fmaf(v0.y, m0, a0y);
            a1x = fmaf(v1.x, m1, a1x);  a1y = fmaf(v1.y, m1, a1y);
            a2x = fmaf(v2.x, m2, a2x);  a2y = fmaf(v2.y, m2, a2y);
            a3x = fmaf(v3.x, m3, a3x);  a3y = fmaf(v3.y, m3, a3y);
        }
        for (; j < e2; j++) {
            int   r  = srow[j];
            float nm = snorm[j];
            float2 v = __ldg(&xw2[r * 32 + lane]);
            a0x = fmaf(v.x, nm, a0x);  a0y = fmaf(v.y, nm, a0y);
        }
        float ax = (a0x + a1x) + (a2x + a3x);
        float ay = (a0y + a1y) + (a2y + a3y);
        ax = fmaxf(ax + bx0, 0.f);
        ay = fmaxf(ay + bx1, 0.f);
        h2[n * 32 + lane] = make_float2(ax, ay);
    }
}

// ---------------------------------------------------------------------------
// K3: classifier  logits += h[G,32768] @ lw[C,32768]^T
//     Warp-per-graph, lane = consecutive float4 -> EVERY load is a fully
//     coalesced 512B LDG.128 transaction. 64 FMA per 17 loads -> FFMA-bound.
//     grid (16 ksplit, 32 gtiles), block 256 = 8 warps = 8 graphs.
// ---------------------------------------------------------------------------
__global__ __launch_bounds__(256) void k3_cls(const float* __restrict__ lw)
{
    const int tid  = threadIdx.x;
    const int wid  = tid >> 5;
    const int lane = tid & 31;

    const int g       = blockIdx.y * 8 + wid;
    const int kbase4  = blockIdx.x * 512;        // float4 units (2048 floats)

    const float4* h4 = (const float4*)(g_h + (size_t)g * NK);

    float acc[Cc];
    #pragma unroll
    for (int c = 0; c < Cc; c++) acc[c] = 0.f;

    #pragma unroll 4
    for (int j = 0; j < 16; j++) {
        const int k4 = kbase4 + j * 32 + lane;
        float4 hv = __ldg(&h4[k4]);
        #pragma unroll
        for (int c = 0; c < Cc; c++) {
            float4 wv = __ldg((const float4*)(lw + (size_t)c * NK) + k4);
            acc[c] = fmaf(hv.x, wv.x,
                     fmaf(hv.y, wv.y,
                     fmaf(hv.z, wv.z,
                     fmaf(hv.w, wv.w, acc[c]))));
        }
    }

    // lane-reduce each class sum, lane 0 commits
    #pragma unroll
    for (int c = 0; c < Cc; c++) {
        float v = acc[c];
        #pragma unroll
        for (int o = 16; o > 0; o >>= 1)
            v += __shfl_xor_sync(0xffffffffu, v, o);
        acc[c] = v;
    }
    if (lane == 0) {
        #pragma unroll
        for (int c = 0; c < Cc; c++)
            atomicAdd(&g_logits[(size_t)g * Cc + c], acc[c]);
    }
}

// ---------------------------------------------------------------------------
// K4: bias + log_softmax over [G, 16]
// ---------------------------------------------------------------------------
__global__ __launch_bounds__(256) void k4_lsm(const float* __restrict__ lb,
                                              float* __restrict__ out)
{
    const int tid = threadIdx.x;
    const int g   = blockIdx.x * 16 + (tid >> 4);
    const int c   = tid & 15;

    float s = g_logits[g * Cc + c] + lb[c];
    float m = s;
    #pragma unroll
    for (int o = 8; o > 0; o >>= 1)
        m = fmaxf(m, __shfl_xor_sync(0xffffffffu, m, o, 16));
    float se = expf(s - m);
    #pragma unroll
    for (int o = 8; o > 0; o >>= 1)
        se += __shfl_xor_sync(0xffffffffu, se, o, 16);
    out[g * Cc + c] = (s - m) - logf(se);
}

// ---------------------------------------------------------------------------
extern "C" void kernel_launch(void* const* d_in, const int* in_sizes, int n_in,
                              void* d_out, int out_size)
{
    const float* x  = (const float*)d_in[0];   // [G, N, F_IN]
    const int*   ei = (const int*)  d_in[1];   // [G, 2, E]
    const float* cw = (const float*)d_in[2];   // [F_OUT, F_IN]
    const float* cb = (const float*)d_in[3];   // [F_OUT]
    const float* lw = (const float*)d_in[4];   // [C, N*F_OUT]
    const float* lb = (const float*)d_in[5];   // [C]
    float* out = (float*)d_out;                // [G, C]

    k1_xw <<<dim3(Nn / 64, Gg), 256>>>(x, cw);
    k2_agg<<<dim3(Gg, 2), 512>>>(ei, cb);
    k3_cls<<<dim3(16, Gg / 8), 256>>>(lw);
    k4_lsm<<<Gg / 16, 256>>>(lb, out);
}